// round 1
// baseline (speedup 1.0000x reference)
#include <cuda_runtime.h>

#define BB 4
#define CIN 64
#define CO 128
#define HH 256
#define WW 256
#define HWP 65536
#define NOUT (BB*4*HWP)   // 1048576

// scratch: h = conv1(x)  [B, 128, 256, 256] fp32 = 128 MB
__device__ float g_h[(size_t)BB * CO * HWP];

// ---------------------------------------------------------------------------
// Kernel 1: 3x3 conv, 64 -> 128, pad 1, + bias. Implicit GEMM tiling.
// Block: 256 threads, computes 128 cout x (4 rows x 32 cols) pixels.
// Thread: 16 couts x 4 consecutive cols (64 accumulators).
// ---------------------------------------------------------------------------
__global__ __launch_bounds__(256, 2) void conv1_kernel(
    const float* __restrict__ x, const float* __restrict__ Wc,
    const float* __restrict__ bc)
{
    __shared__ float sW[72 * 129];     // [rk = ci*9+k][cout], stride 129 (odd: STS conflict-free)
    __shared__ float sX[8 * 6 * 35];   // [ci][row 0..5][col 0..33], stride 35

    const int b  = blockIdx.z;
    const int y0 = blockIdx.y * 4;
    const int x0 = blockIdx.x * 32;
    const int tid  = threadIdx.x;
    const int cg   = tid >> 5;          // cout group 0..7 (16 couts each)
    const int q    = tid & 31;
    const int row  = q >> 3;            // 0..3
    const int colq = (q & 7) * 4;       // 0,4,...,28

    float acc[16][4];
#pragma unroll
    for (int m = 0; m < 16; m++)
#pragma unroll
        for (int j = 0; j < 4; j++) acc[m][j] = 0.f;

    for (int cc = 0; cc < 8; cc++) {
        const int cb = cc * 8;
        __syncthreads();   // previous chunk's compute done before overwrite

        // weights: gaddr = cout*576 + cb*9 + rk (linear in rk -> coalesced)
#pragma unroll 4
        for (int i = tid; i < 128 * 72; i += 256) {
            int cout = i / 72, rk = i % 72;
            sW[rk * 129 + cout] = Wc[cout * 576 + cb * 9 + rk];
        }
        // x tile with halo: 8 ci x 6 rows x 34 cols
        for (int i = tid; i < 8 * 6 * 34; i += 256) {
            int ci = i / 204, r = (i / 34) % 6, c = i % 34;
            int gy = y0 - 1 + r, gx = x0 - 1 + c;
            float v = 0.f;
            if (gy >= 0 && gy < HH && gx >= 0 && gx < WW)
                v = x[(((size_t)b * CIN + cb + ci) * HH + gy) * WW + gx];
            sX[(ci * 6 + r) * 35 + c] = v;
        }
        __syncthreads();

#pragma unroll 2
        for (int ci = 0; ci < 8; ci++) {
#pragma unroll
            for (int ky = 0; ky < 3; ky++) {
                const float* xr = &sX[(ci * 6 + row + ky) * 35 + colq];
#pragma unroll
                for (int kx = 0; kx < 3; kx++) {
                    float xv0 = xr[kx + 0];
                    float xv1 = xr[kx + 1];
                    float xv2 = xr[kx + 2];
                    float xv3 = xr[kx + 3];
                    const float* wr = &sW[(ci * 9 + ky * 3 + kx) * 129 + cg * 16];
#pragma unroll
                    for (int m = 0; m < 16; m++) {
                        float w = wr[m];   // broadcast LDS (uniform within warp)
                        acc[m][0] += w * xv0;
                        acc[m][1] += w * xv1;
                        acc[m][2] += w * xv2;
                        acc[m][3] += w * xv3;
                    }
                }
            }
        }
    }

#pragma unroll
    for (int m = 0; m < 16; m++) {
        int cout = cg * 16 + m;
        float bb = bc[cout];
        float4 v = make_float4(acc[m][0] + bb, acc[m][1] + bb,
                               acc[m][2] + bb, acc[m][3] + bb);
        *reinterpret_cast<float4*>(
            &g_h[(((size_t)b * CO + cout) * HH + y0 + row) * WW + x0 + colq]) = v;
    }
}

// ---------------------------------------------------------------------------
// Kernel 2: MC dropout samples -> mean + unbiased variance.
// One thread per pixel. Wm[t,o,c] = W_out[o,c]*mask[t,c] staged in smem.
// Writes EU to out[NOUT..2N), mean to out[2N..3N).
// ---------------------------------------------------------------------------
__global__ __launch_bounds__(256, 2) void mc_kernel(
    const float* __restrict__ lms, const float* __restrict__ Wo,
    const float* __restrict__ bo, const float* __restrict__ masks,
    float* __restrict__ out)
{
    __shared__ float sWm[128 * 64];   // [c][t][o], o fastest (float4 per (c,t))
    const int tid = threadIdx.x;
    for (int i = tid; i < 128 * 64; i += 256) {
        int c = i >> 6, t = (i >> 2) & 15, o = i & 3;
        sWm[i] = Wo[o * 128 + c] * masks[t * 128 + c];
    }
    __syncthreads();

    int p   = blockIdx.x * 256 + tid;
    int b   = p >> 16;
    int pix = p & 65535;
    const float* hb = g_h + (size_t)b * CO * HWP + pix;
    const float4* sWm4 = reinterpret_cast<const float4*>(sWm);

    float acc[16][4];
#pragma unroll
    for (int t = 0; t < 16; t++)
#pragma unroll
        for (int o = 0; o < 4; o++) acc[t][o] = 0.f;

#pragma unroll 4
    for (int c = 0; c < 128; c++) {
        float hv = __ldg(hb + (size_t)c * HWP);
        const float4* wr = &sWm4[c * 16];
#pragma unroll
        for (int t = 0; t < 16; t++) {
            float4 w = wr[t];   // broadcast LDS.128
            acc[t][0] += w.x * hv;
            acc[t][1] += w.y * hv;
            acc[t][2] += w.z * hv;
            acc[t][3] += w.w * hv;
        }
    }

    float bov0 = bo[0], bov1 = bo[1], bov2 = bo[2], bov3 = bo[3];
#pragma unroll
    for (int o = 0; o < 4; o++) {
        float bb = (o == 0) ? bov0 : (o == 1) ? bov1 : (o == 2) ? bov2 : bov3;
        float s[16];
        float sum = 0.f;
#pragma unroll
        for (int t = 0; t < 16; t++) {
            float v = tanhf(acc[t][o] + bb);
            s[t] = v;
            sum += v;
        }
        float mn = sum * 0.0625f;
        float var = 0.f;
#pragma unroll
        for (int t = 0; t < 16; t++) {
            float d = s[t] - mn;
            var += d * d;
        }
        var *= (1.f / 15.f);
        int oidx = (b * 4 + o) * HWP + pix;
        out[NOUT + oidx]     = var;              // EU (lms is const over t -> no var contrib)
        out[2 * NOUT + oidx] = mn + lms[oidx];   // mean
    }
}

// ---------------------------------------------------------------------------
// Kernel 3: AU = sigmoid(3x3 conv 128->4 on h + bias). Writes out[0..NOUT).
// Block: 256 threads, 32x32 pixel tile. Thread: 4 couts x 4 cols.
// ---------------------------------------------------------------------------
__global__ __launch_bounds__(256, 2) void au_kernel(
    const float* __restrict__ Wa, const float* __restrict__ ba,
    float* __restrict__ out)
{
    __shared__ float sWa[128 * 9 * 4];   // [(ci*9+k)*4 + o]
    __shared__ float sX[4 * 34 * 35];    // chunk of 4 ci, 34x34 tile, stride 35

    const int b  = blockIdx.z;
    const int y0 = blockIdx.y * 32;
    const int x0 = blockIdx.x * 32;
    const int tid  = threadIdx.x;
    const int row  = tid >> 3;           // 0..31
    const int colq = (tid & 7) * 4;      // 0..28

    for (int i = tid; i < 128 * 36; i += 256) {
        int ci = i / 36, rem = i % 36, k = rem >> 2, o = rem & 3;
        sWa[i] = Wa[(o * 128 + ci) * 9 + k];
    }

    float acc[4][4] = {};
    for (int cc = 0; cc < 32; cc++) {
        __syncthreads();
        for (int i = tid; i < 4 * 34 * 34; i += 256) {
            int ci = i / 1156, r = (i / 34) % 34, c = i % 34;
            int gy = y0 - 1 + r, gx = x0 - 1 + c;
            float v = 0.f;
            if (gy >= 0 && gy < HH && gx >= 0 && gx < WW)
                v = g_h[(((size_t)b * CO + cc * 4 + ci) * HH + gy) * WW + gx];
            sX[(ci * 34 + r) * 35 + c] = v;
        }
        __syncthreads();

#pragma unroll
        for (int ci = 0; ci < 4; ci++) {
#pragma unroll
            for (int ky = 0; ky < 3; ky++) {
                const float* xr = &sX[(ci * 34 + row + ky) * 35 + colq];
#pragma unroll
                for (int kx = 0; kx < 3; kx++) {
                    float xv0 = xr[kx + 0];
                    float xv1 = xr[kx + 1];
                    float xv2 = xr[kx + 2];
                    float xv3 = xr[kx + 3];
                    float4 w = *reinterpret_cast<const float4*>(
                        &sWa[((cc * 4 + ci) * 9 + ky * 3 + kx) * 4]);
                    acc[0][0] += w.x * xv0; acc[0][1] += w.x * xv1;
                    acc[0][2] += w.x * xv2; acc[0][3] += w.x * xv3;
                    acc[1][0] += w.y * xv0; acc[1][1] += w.y * xv1;
                    acc[1][2] += w.y * xv2; acc[1][3] += w.y * xv3;
                    acc[2][0] += w.z * xv0; acc[2][1] += w.z * xv1;
                    acc[2][2] += w.z * xv2; acc[2][3] += w.z * xv3;
                    acc[3][0] += w.w * xv0; acc[3][1] += w.w * xv1;
                    acc[3][2] += w.w * xv2; acc[3][3] += w.w * xv3;
                }
            }
        }
    }

#pragma unroll
    for (int o = 0; o < 4; o++) {
        float bb = ba[o];
        float4 v;
        v.x = 1.f / (1.f + expf(-(acc[o][0] + bb)));
        v.y = 1.f / (1.f + expf(-(acc[o][1] + bb)));
        v.z = 1.f / (1.f + expf(-(acc[o][2] + bb)));
        v.w = 1.f / (1.f + expf(-(acc[o][3] + bb)));
        *reinterpret_cast<float4*>(
            &out[((size_t)(b * 4 + o) * HH + y0 + row) * WW + x0 + colq]) = v;
    }
}

// ---------------------------------------------------------------------------
extern "C" void kernel_launch(void* const* d_in, const int* in_sizes, int n_in,
                              void* d_out, int out_size) {
    const float* x     = (const float*)d_in[0];
    const float* lms   = (const float*)d_in[1];
    const float* Wc    = (const float*)d_in[2];
    const float* bc    = (const float*)d_in[3];
    const float* Wo    = (const float*)d_in[4];
    const float* bo    = (const float*)d_in[5];
    const float* Wa    = (const float*)d_in[6];
    const float* ba    = (const float*)d_in[7];
    const float* masks = (const float*)d_in[8];
    float* out = (float*)d_out;

    conv1_kernel<<<dim3(8, 64, 4), 256>>>(x, Wc, bc);
    mc_kernel<<<1024, 256>>>(lms, Wo, bo, masks, out);
    au_kernel<<<dim3(8, 8, 4), 256>>>(Wa, ba, out);
}

// round 2
// speedup vs baseline: 1.1984x; 1.1984x over previous
#include <cuda_runtime.h>

#define BB 4
#define CIN 64
#define CO 128
#define HH 256
#define WW 256
#define HWP 65536
#define NOUT (BB*4*HWP)   // 1048576

typedef unsigned long long u64;

// scratch: h = conv1(x)  [B, 128, 256, 256] fp32 = 128 MB
__device__ float g_h[(size_t)BB * CO * HWP];
// pre-transposed conv1 weights: [rk = ci*9+k][cout]  (576 x 128)
__device__ float g_Wt[576 * 128];

// ---- f32x2 helpers (packed 2xfp32 FMA — sm_103a FFMA2 path) -------------
__device__ __forceinline__ void fma2(u64& d, u64 a, u64 b) {
    asm("fma.rn.f32x2 %0, %1, %2, %0;" : "+l"(d) : "l"(a), "l"(b));
}
__device__ __forceinline__ u64 dup2(float x) {
    u64 d; asm("mov.b64 %0, {%1, %1};" : "=l"(d) : "f"(x)); return d;
}
__device__ __forceinline__ float2 unpk(u64 d) {
    float2 r; asm("mov.b64 {%0, %1}, %2;" : "=f"(r.x), "=f"(r.y) : "l"(d));
    return r;
}

// ---------------------------------------------------------------------------
// Kernel 0: transpose conv1 weights -> [rk][cout] for vectorized smem loads
// ---------------------------------------------------------------------------
__global__ void transpose_w(const float* __restrict__ Wc) {
    int i = blockIdx.x * 256 + threadIdx.x;   // < 576*128
    int cout = i & 127, rk = i >> 7;
    g_Wt[rk * 128 + cout] = Wc[cout * 576 + rk];
}

// ---------------------------------------------------------------------------
// Kernel 1: 3x3 conv, 64 -> 128, pad 1, + bias.
// Block: 256 threads, 128 cout x (4 rows x 32 cols). Thread: 16 couts x 4 cols,
// accumulated as 8 f32x2 cout-pairs x 4 pixels.
// ---------------------------------------------------------------------------
__global__ __launch_bounds__(256, 2) void conv1_kernel(
    const float* __restrict__ x, const float* __restrict__ bc)
{
    __shared__ float sW[72 * 128];   // [rk][cout], 16B-aligned cout groups
    __shared__ float sX[8 * 6 * 36]; // [ci][row 0..5][col 0..33], stride 36 (16B aligned)

    const int b  = blockIdx.z;
    const int y0 = blockIdx.y * 4;
    const int x0 = blockIdx.x * 32;
    const int tid  = threadIdx.x;
    const int cg   = tid >> 5;          // cout group 0..7 (16 couts)
    const int q    = tid & 31;
    const int row  = q >> 3;            // 0..3
    const int colq = (q & 7) * 4;       // 0..28

    u64 acc[8][4];
#pragma unroll
    for (int p = 0; p < 8; p++)
#pragma unroll
        for (int j = 0; j < 4; j++) acc[p][j] = 0ull;

    for (int cc = 0; cc < 8; cc++) {
        __syncthreads();   // previous chunk's compute done before overwrite

        // weights: contiguous slab of g_Wt (coalesced, STS conflict-free)
#pragma unroll 4
        for (int i = tid; i < 72 * 128; i += 256)
            sW[i] = g_Wt[cc * (72 * 128) + i];

        // x tile with halo: 8 ci x 6 rows x 34 cols
        for (int i = tid; i < 8 * 6 * 34; i += 256) {
            int ci = i / 204, r = (i / 34) % 6, c = i % 34;
            int gy = y0 - 1 + r, gx = x0 - 1 + c;
            float v = 0.f;
            if (gy >= 0 && gy < HH && gx >= 0 && gx < WW)
                v = x[(((size_t)b * CIN + cc * 8 + ci) * HH + gy) * WW + gx];
            sX[(ci * 6 + r) * 36 + c] = v;
        }
        __syncthreads();

#pragma unroll 2
        for (int ci = 0; ci < 8; ci++) {
#pragma unroll
            for (int ky = 0; ky < 3; ky++) {
                const float* xr = &sX[(ci * 6 + row + ky) * 36 + colq];
                float4 xa = *reinterpret_cast<const float4*>(xr);
                float4 xb = *reinterpret_cast<const float4*>(xr + 4);
                u64 xd[6];
                xd[0] = dup2(xa.x); xd[1] = dup2(xa.y);
                xd[2] = dup2(xa.z); xd[3] = dup2(xa.w);
                xd[4] = dup2(xb.x); xd[5] = dup2(xb.y);
#pragma unroll
                for (int kx = 0; kx < 3; kx++) {
                    const ulonglong2* wp = reinterpret_cast<const ulonglong2*>(
                        &sW[(ci * 9 + ky * 3 + kx) * 128 + cg * 16]);
                    ulonglong2 wA = wp[0];   // cout pairs 0,1
                    ulonglong2 wB = wp[1];   // pairs 2,3
                    ulonglong2 wC = wp[2];   // pairs 4,5
                    ulonglong2 wD = wp[3];   // pairs 6,7
#pragma unroll
                    for (int j = 0; j < 4; j++) {
                        u64 xv = xd[kx + j];
                        fma2(acc[0][j], wA.x, xv);
                        fma2(acc[1][j], wA.y, xv);
                        fma2(acc[2][j], wB.x, xv);
                        fma2(acc[3][j], wB.y, xv);
                        fma2(acc[4][j], wC.x, xv);
                        fma2(acc[5][j], wC.y, xv);
                        fma2(acc[6][j], wD.x, xv);
                        fma2(acc[7][j], wD.y, xv);
                    }
                }
            }
        }
    }

#pragma unroll
    for (int p = 0; p < 8; p++) {
        int c0 = cg * 16 + 2 * p;
        float b0 = bc[c0], b1 = bc[c0 + 1];
        float4 v0, v1;
        float2 f;
        f = unpk(acc[p][0]); v0.x = f.x + b0; v1.x = f.y + b1;
        f = unpk(acc[p][1]); v0.y = f.x + b0; v1.y = f.y + b1;
        f = unpk(acc[p][2]); v0.z = f.x + b0; v1.z = f.y + b1;
        f = unpk(acc[p][3]); v0.w = f.x + b0; v1.w = f.y + b1;
        size_t base = (((size_t)b * CO + c0) * HH + y0 + row) * WW + x0 + colq;
        *reinterpret_cast<float4*>(&g_h[base]) = v0;
        *reinterpret_cast<float4*>(&g_h[base + (size_t)HH * WW]) = v1;
    }
}

// ---------------------------------------------------------------------------
// Kernel 2: MC dropout samples -> mean + unbiased variance (f32x2 over o-pairs)
// ---------------------------------------------------------------------------
__global__ __launch_bounds__(256, 2) void mc_kernel(
    const float* __restrict__ lms, const float* __restrict__ Wo,
    const float* __restrict__ bo, const float* __restrict__ masks,
    float* __restrict__ out)
{
    __shared__ float sWm[128 * 64];   // [c][t][o], o fastest (16B per (c,t))
    const int tid = threadIdx.x;
    for (int i = tid; i < 128 * 64; i += 256) {
        int c = i >> 6, t = (i >> 2) & 15, o = i & 3;
        sWm[i] = Wo[o * 128 + c] * masks[t * 128 + c];
    }
    __syncthreads();

    int p   = blockIdx.x * 256 + tid;
    int b   = p >> 16;
    int pix = p & 65535;
    const float* hb = g_h + (size_t)b * CO * HWP + pix;

    u64 acc01[16], acc23[16];
#pragma unroll
    for (int t = 0; t < 16; t++) { acc01[t] = 0ull; acc23[t] = 0ull; }

#pragma unroll 4
    for (int c = 0; c < 128; c++) {
        float hv = __ldg(hb + (size_t)c * HWP);
        u64 hd = dup2(hv);
        const ulonglong2* wr = reinterpret_cast<const ulonglong2*>(&sWm[c * 64]);
#pragma unroll
        for (int t = 0; t < 16; t++) {
            ulonglong2 w = wr[t];   // broadcast LDS.128
            fma2(acc01[t], w.x, hd);
            fma2(acc23[t], w.y, hd);
        }
    }

    float a[16][4];
#pragma unroll
    for (int t = 0; t < 16; t++) {
        float2 f01 = unpk(acc01[t]);
        float2 f23 = unpk(acc23[t]);
        a[t][0] = f01.x; a[t][1] = f01.y; a[t][2] = f23.x; a[t][3] = f23.y;
    }

#pragma unroll
    for (int o = 0; o < 4; o++) {
        float bb = bo[o];
        float s[16];
        float sum = 0.f;
#pragma unroll
        for (int t = 0; t < 16; t++) {
            float v = tanhf(a[t][o] + bb);
            s[t] = v;
            sum += v;
        }
        float mn = sum * 0.0625f;
        float var = 0.f;
#pragma unroll
        for (int t = 0; t < 16; t++) {
            float d = s[t] - mn;
            var += d * d;
        }
        var *= (1.f / 15.f);
        int oidx = (b * 4 + o) * HWP + pix;
        out[NOUT + oidx]     = var;              // EU
        out[2 * NOUT + oidx] = mn + lms[oidx];   // mean
    }
}

// ---------------------------------------------------------------------------
// Kernel 3: AU = sigmoid(3x3 conv 128->4 on h + bias). f32x2 over o-pairs.
// ---------------------------------------------------------------------------
__global__ __launch_bounds__(256, 2) void au_kernel(
    const float* __restrict__ Wa, const float* __restrict__ ba,
    float* __restrict__ out)
{
    __shared__ float sWa[128 * 9 * 4];   // [(ci*9+k)*4 + o]  (16B aligned per k)
    __shared__ float sX[4 * 34 * 36];    // chunk of 4 ci, 34x34 tile, stride 36

    const int b  = blockIdx.z;
    const int y0 = blockIdx.y * 32;
    const int x0 = blockIdx.x * 32;
    const int tid  = threadIdx.x;
    const int row  = tid >> 3;           // 0..31
    const int colq = (tid & 7) * 4;      // 0..28

    for (int i = tid; i < 128 * 36; i += 256) {
        int ci = i / 36, rem = i % 36, k = rem >> 2, o = rem & 3;
        sWa[i] = Wa[(o * 128 + ci) * 9 + k];
    }

    u64 acc01[4], acc23[4];
#pragma unroll
    for (int j = 0; j < 4; j++) { acc01[j] = 0ull; acc23[j] = 0ull; }

    for (int cc = 0; cc < 32; cc++) {
        __syncthreads();
        for (int i = tid; i < 4 * 34 * 34; i += 256) {
            int ci = i / 1156, r = (i / 34) % 34, c = i % 34;
            int gy = y0 - 1 + r, gx = x0 - 1 + c;
            float v = 0.f;
            if (gy >= 0 && gy < HH && gx >= 0 && gx < WW)
                v = g_h[(((size_t)b * CO + cc * 4 + ci) * HH + gy) * WW + gx];
            sX[(ci * 34 + r) * 36 + c] = v;
        }
        __syncthreads();

#pragma unroll
        for (int ci = 0; ci < 4; ci++) {
#pragma unroll
            for (int ky = 0; ky < 3; ky++) {
                const float* xr = &sX[(ci * 34 + row + ky) * 36 + colq];
                float4 xa = *reinterpret_cast<const float4*>(xr);
                float4 xb = *reinterpret_cast<const float4*>(xr + 4);
                u64 xd[6];
                xd[0] = dup2(xa.x); xd[1] = dup2(xa.y);
                xd[2] = dup2(xa.z); xd[3] = dup2(xa.w);
                xd[4] = dup2(xb.x); xd[5] = dup2(xb.y);
#pragma unroll
                for (int kx = 0; kx < 3; kx++) {
                    ulonglong2 w = *reinterpret_cast<const ulonglong2*>(
                        &sWa[((cc * 4 + ci) * 9 + ky * 3 + kx) * 4]);
#pragma unroll
                    for (int j = 0; j < 4; j++) {
                        fma2(acc01[j], w.x, xd[kx + j]);
                        fma2(acc23[j], w.y, xd[kx + j]);
                    }
                }
            }
        }
    }

    float av[4][4];
#pragma unroll
    for (int j = 0; j < 4; j++) {
        float2 f01 = unpk(acc01[j]);
        float2 f23 = unpk(acc23[j]);
        av[0][j] = f01.x; av[1][j] = f01.y; av[2][j] = f23.x; av[3][j] = f23.y;
    }

#pragma unroll
    for (int o = 0; o < 4; o++) {
        float bb = ba[o];
        float4 v;
        v.x = 1.f / (1.f + expf(-(av[o][0] + bb)));
        v.y = 1.f / (1.f + expf(-(av[o][1] + bb)));
        v.z = 1.f / (1.f + expf(-(av[o][2] + bb)));
        v.w = 1.f / (1.f + expf(-(av[o][3] + bb)));
        *reinterpret_cast<float4*>(
            &out[((size_t)(b * 4 + o) * HH + y0 + row) * WW + x0 + colq]) = v;
    }
}

// ---------------------------------------------------------------------------
extern "C" void kernel_launch(void* const* d_in, const int* in_sizes, int n_in,
                              void* d_out, int out_size) {
    const float* x     = (const float*)d_in[0];
    const float* lms   = (const float*)d_in[1];
    const float* Wc    = (const float*)d_in[2];
    const float* bc    = (const float*)d_in[3];
    const float* Wo    = (const float*)d_in[4];
    const float* bo    = (const float*)d_in[5];
    const float* Wa    = (const float*)d_in[6];
    const float* ba    = (const float*)d_in[7];
    const float* masks = (const float*)d_in[8];
    float* out = (float*)d_out;

    transpose_w<<<288, 256>>>(Wc);
    conv1_kernel<<<dim3(8, 64, 4), 256>>>(x, bc);
    mc_kernel<<<1024, 256>>>(lms, Wo, bo, masks, out);
    au_kernel<<<dim3(8, 8, 4), 256>>>(Wa, ba, out);
}